// round 2
// baseline (speedup 1.0000x reference)
#include <cuda_runtime.h>

// ENC_GRUTurbo: fused 2-layer minGRU x2 nets + global standardize.
// B=256, L=2048, H=64. One CTA per (batch, net). fp32 with packed f32x2 FMA.
// Key tricks: binary-input gate precompute, j-pair FFMA2 (no dup MOVs),
// smem aliasing (h0 / ab union) for occupancy 3+.

#define BB 256
#define LL 2048
#define HH 64
#define TT 32
#define NC (LL / TT)
#define NTOT (BB * LL * 2)

typedef unsigned long long ull;

__device__ double g_sum;
__device__ double g_sumsq;

__device__ __forceinline__ ull fma2(ull a, ull b, ull c) {
    ull d;
    asm("fma.rn.f32x2 %0, %1, %2, %3;" : "=l"(d) : "l"(a), "l"(b), "l"(c));
    return d;
}
__device__ __forceinline__ ull pack2(float x, float y) {
    ull d;
    asm("mov.b64 %0, {%1, %2};" : "=l"(d) : "f"(x), "f"(y));
    return d;
}
__device__ __forceinline__ float2 unpack2(ull v) {
    float x, y;
    asm("mov.b64 {%0, %1}, %2;" : "=f"(x), "=f"(y) : "l"(v));
    return make_float2(x, y);
}
__device__ __forceinline__ float sigmoidf(float x) {
    return 1.0f / (1.0f + __expf(-x));
}

struct Params {
    const float* inputs;   // [B*L], values in {0,1}
    const int*   p;        // [L]
    const float* w[20];    // net0: wz0,bz0,wh0,bh0,wz1,bz1,wh1,bh1,wo,bo ; net1 same
    float*       out;      // [B*L*2]
};

// ---- shared memory layout (bytes) ----
// Wq   : [64 c][32 jp] ulonglong2 (wz-pair, wh-pair)         = 32768
// union:
//   h0d: [64 c][33] ull  (duplicated h0, padded stride)      = 16896
//   ab : [32 t][64 c] float2 (a1, b1) -> .x becomes h*wo     = 16384
// xs   : [2][32] float                                        = 256
#define OFF_W   0
#define OFF_U   32768
#define OFF_XS  (32768 + 16896)
#define SMEM_BYTES (OFF_XS + 2 * TT * 4)

__global__ void zero_accum_kernel() {
    g_sum = 0.0;
    g_sumsq = 0.0;
}

__global__ void __launch_bounds__(256, 3) gru_main_kernel(Params prm) {
    extern __shared__ char sm[];
    ulonglong2* Wq  = (ulonglong2*)(sm + OFF_W);   // [c*32 + jp]
    ull*        h0d = (ull*)(sm + OFF_U);          // [c*33 + t]
    float2*     ab  = (float2*)(sm + OFF_U);       // [t*64 + c]
    float*      xs  = (float*)(sm + OFF_XS);       // [kb*32 + t]

    const int tid = threadIdx.x;
    const int b   = blockIdx.x >> 1;
    const int net = blockIdx.x & 1;

    const float* const* w = prm.w + net * 10;
    const float* wz1 = w[4];
    const float* wh1 = w[6];

    // ---- weights -> smem, interleaved (wz-pair, wh-pair) per (c, jp) ----
    for (int i = tid; i < HH * 32; i += 256) {
        int c = i >> 5, jp = i & 31;
        float2 wzp = *(const float2*)&wz1[c * HH + 2 * jp];
        float2 whp = *(const float2*)&wh1[c * HH + 2 * jp];
        ulonglong2 q;
        q.x = pack2(wzp.x, wzp.y);
        q.y = pack2(whp.x, whp.y);
        Wq[i] = q;
    }

    // ---- per-thread constants ----
    // scan threads (tid < 64): layer-0 gate has only 2 states (x in {0,1})
    float a00 = 0.f, b00 = 0.f, a01 = 0.f, b01 = 0.f, woc = 0.f;
    if (tid < HH) {
        float wz = w[0][tid], bz = w[1][tid];
        float wh = w[2][tid], bh = w[3][tid];
        float z0 = sigmoidf(bz);          // x = 0
        float z1 = sigmoidf(wz + bz);     // x = 1 (fma(1,w,b) == w+b exactly)
        a00 = 1.0f - z0;  b00 = z0 * bh;
        a01 = 1.0f - z1;  b01 = z1 * (wh + bh);
        woc = w[8][tid];
    }
    const int jp = tid & 31;       // column pair: j = 2jp, 2jp+1
    const int tg = tid >> 5;       // 8 groups x 4 timesteps
    const int t0 = tg * 4;
    const ull bz2 = pack2(w[5][2 * jp], w[5][2 * jp + 1]);
    const ull bh2 = pack2(w[7][2 * jp], w[7][2 * jp + 1]);
    const float bo = w[9][0];

    // preload first x chunk
    if (tid < TT) {
        int src = net ? prm.p[tid] : tid;
        xs[tid] = prm.inputs[(size_t)b * LL + src];
    }
    __syncthreads();

    float h0c = 0.0f, h1c = 0.0f;     // scan carries (tid < 64)
    float lsum = 0.0f, lsq = 0.0f;    // stats (tid < 32)

    for (int k = 0; k < NC; ++k) {
        const int kb = k & 1;

        // ---- phase b: layer-0 scan (binary gate), write duplicated h0 ----
        if (tid < HH) {
            float h = h0c;
            #pragma unroll
            for (int t = 0; t < TT; ++t) {
                float xv = xs[kb * TT + t];
                float a  = xv > 0.5f ? a01 : a00;
                float bb = xv > 0.5f ? b01 : b00;
                h = fmaf(a, h, bb);
                h0d[tid * 33 + t] = pack2(h, h);
            }
            h0c = h;
        }
        __syncthreads();

        // ---- phase c: layer-1 matvec, f32x2 packed over column pairs ----
        ull az[4], ah[4];
        #pragma unroll
        for (int p = 0; p < 4; ++p) { az[p] = bz2; ah[p] = bh2; }
        {
            const ulonglong2* wq = Wq + jp;
            const ull* hp = h0d + t0;
            #pragma unroll 8
            for (int c = 0; c < HH; ++c) {
                ulonglong2 wv = wq[c * 32];            // LDS.128: wz-pair, wh-pair
                #pragma unroll
                for (int p = 0; p < 4; ++p) {
                    ull hv = hp[c * 33 + p];           // broadcast LDS.64 (h, h)
                    az[p] = fma2(hv, wv.x, az[p]);
                    ah[p] = fma2(hv, wv.y, ah[p]);
                }
            }
        }
        __syncthreads();   // all h0d reads done: ab may overwrite the union

        // ---- epilogue: gate nonlinearity, store (a1,b1) ----
        #pragma unroll
        for (int p = 0; p < 4; ++p) {
            float2 zz = unpack2(az[p]);
            float2 hh = unpack2(ah[p]);
            float z0 = sigmoidf(zz.x);
            float z1 = sigmoidf(zz.y);
            float4 v;
            v.x = 1.0f - z0;  v.y = z0 * hh.x;
            v.z = 1.0f - z1;  v.w = z1 * hh.y;
            *(float4*)&ab[(t0 + p) * HH + 2 * jp] = v;  // STS.128
        }
        __syncthreads();

        // ---- phase d: layer-1 scan + Wo product (in-place .x) ----
        if (tid < HH) {
            float h = h1c;
            #pragma unroll
            for (int t = 0; t < TT; ++t) {
                float2 v = ab[t * HH + tid];
                h = fmaf(v.x, h, v.y);
                ab[t * HH + tid].x = h * woc;
            }
            h1c = h;
        } else if (tid < HH + TT) {
            // idle warp prefetches next x chunk
            if (k + 1 < NC) {
                int lane = tid - HH;
                int g = (k + 1) * TT + lane;
                int src = net ? prm.p[g] : g;
                xs[(1 - kb) * TT + lane] = prm.inputs[(size_t)b * LL + src];
            }
        }
        __syncthreads();

        // ---- phase e: output projection sum + stats ----
        if (tid < TT) {
            float ssum = bo;
            #pragma unroll 8
            for (int i = 0; i < HH; ++i) {
                int c = (tid + i) & 63;                // rotated, 2-way max
                ssum += ab[tid * HH + c].x;
            }
            int tglob = k * TT + tid;
            prm.out[((size_t)b * LL + tglob) * 2 + net] = ssum;
            lsum += ssum;
            lsq  += ssum * ssum;
        }
        __syncthreads();   // protect ab (aliased by next chunk's h0d writes)
    }

    // ---- per-CTA stats: warp 0 shuffle-reduce -> global double atomics ----
    if (tid < 32) {
        #pragma unroll
        for (int o = 16; o > 0; o >>= 1) {
            lsum += __shfl_down_sync(0xffffffffu, lsum, o);
            lsq  += __shfl_down_sync(0xffffffffu, lsq,  o);
        }
        if (tid == 0) {
            atomicAdd(&g_sum,   (double)lsum);
            atomicAdd(&g_sumsq, (double)lsq);
        }
    }
}

__global__ void normalize_kernel(float* out) {
    const double n = (double)NTOT;
    double mean = g_sum / n;
    double var  = (g_sumsq - n * mean * mean) / (n - 1.0);
    float m  = (float)mean;
    float rs = (float)(1.0 / sqrt(var));
    int i = blockIdx.x * blockDim.x + threadIdx.x;
    if (i < NTOT) {
        out[i] = (out[i] - m) * rs;
    }
}

extern "C" void kernel_launch(void* const* d_in, const int* in_sizes, int n_in,
                              void* d_out, int out_size) {
    (void)in_sizes; (void)n_in; (void)out_size;

    Params prm;
    prm.inputs = (const float*)d_in[0];
    prm.p      = (const int*)d_in[1];
    for (int i = 0; i < 20; ++i) {
        prm.w[i] = (const float*)d_in[2 + i];
    }
    prm.out = (float*)d_out;

    cudaFuncSetAttribute(gru_main_kernel,
                         cudaFuncAttributeMaxDynamicSharedMemorySize, SMEM_BYTES);

    zero_accum_kernel<<<1, 1>>>();
    gru_main_kernel<<<BB * 2, 256, SMEM_BYTES>>>(prm);
    normalize_kernel<<<(NTOT + 255) / 256, 256>>>((float*)d_out);
}